// round 6
// baseline (speedup 1.0000x reference)
#include <cuda_runtime.h>
#include <cstdint>

#define NIMG   32
#define CINCH  256
#define COUTCH 256
#define HIMG   56
#define WIMG   56
#define HWSZ   (HIMG*WIMG)           // 3136
#define PDIM   58
#define IMG_PIX (PDIM*PDIM)          // 3364
#define PIX    (NIMG*IMG_PIX)        // 107648 = 841*128
#define GUARD  64
#define TOT_ROWS (GUARD + PIX + GUARD)
#define XROW   512                   // bytes per X_t row: [a1:256 | a2:256]
#define AROW   2304                  // bytes per weight row (9*256)
#define NTILES 841                   // PIX / 128

#define BM 128
#define BN 128
#define NITER 36                     // 9 taps * 4 chunks of 64
#define NSTAGE 4
#define SROW 80                      // padded smem row stride (conflict-free)
#define ST_A  0
#define ST_B1 (128*SROW)             // 10240
#define ST_B2 (2*128*SROW)           // 20480
#define STAGE_BYTES (3*128*SROW)     // 30720
#define SMEM_TOTAL (NSTAGE*STAGE_BYTES)  // 122880

__device__ __align__(256) char g_xt8[(size_t)TOT_ROWS * XROW];   // ~55.4 MB
__device__ __align__(256) char g_aw8[(size_t)COUTCH * AROW];     // ~590 KB

// ---------------- Kernel 1: weight prep (int32 ternary -> int8, [co][tap*256+ci]) ----------------
__global__ void prep_w_kernel(const int* __restrict__ wq) {
    int t = blockIdx.x * 256 + threadIdx.x;
    if (t >= 9 * 256 * 256) return;
    int ci = t & 255, co = (t >> 8) & 255, tap = t >> 16;
    g_aw8[(size_t)co * AROW + tap * 256 + ci] = (char)wq[(co * 256 + ci) * 9 + tap];
}

// ---------------- Kernel 2: zero guards + padded-border rows of X_t ----------------
__global__ void zero_xt_kernel() {
    const int NROWS = 128 + NIMG * 228;      // 7424
    long long t = (long long)blockIdx.x * blockDim.x + threadIdx.x;
    if (t >= (long long)NROWS * 32) return;  // 32 uint4 per row
    int r = (int)(t >> 5), c = (int)(t & 31);
    size_t row;
    if (r < 64) row = (size_t)r;                               // front guard
    else if (r < 128) row = (size_t)GUARD + PIX + (r - 64);    // back guard
    else {
        int rb = r - 128, n = rb / 228, b = rb % 228;
        int ph, pw;
        if (b < 58)        { ph = 0;           pw = b; }
        else if (b < 116)  { ph = 57;          pw = b - 58; }
        else if (b < 172)  { ph = b - 116 + 1; pw = 0; }
        else               { ph = b - 172 + 1; pw = 57; }
        row = (size_t)GUARD + (size_t)n * IMG_PIX + (size_t)ph * PDIM + pw;
    }
    ((uint4*)g_xt8)[row * 32 + c] = make_uint4(0, 0, 0, 0);
}

// ---------------- Kernel 3: activation prep (clamp + 2-level int8 + transpose) ----------------
__global__ void __launch_bounds__(256) prep_x_kernel(const float* __restrict__ x) {
    __shared__ char sp[56 * 516];
    int nh = blockIdx.x;
    int n = nh / HIMG, h = nh % HIMG;
    int tid = threadIdx.x;
    const float c1f = 1.0f / 127.0f;
    for (int idx = tid; idx < 256 * WIMG; idx += 256) {
        int ci = idx / WIMG, w = idx - ci * WIMG;
        float v = x[(((size_t)n * CINCH + ci) * HIMG + h) * WIMG + w];
        v = fminf(fmaxf(v, -1.0f), 1.0f);
        int a1 = __float2int_rn(v * 127.0f);
        float r = fmaf((float)a1, -c1f, v);
        int a2 = __float2int_rn(r * 32258.0f);
        a2 = max(-127, min(127, a2));
        sp[w * 516 + ci]       = (char)a1;
        sp[w * 516 + 256 + ci] = (char)a2;
    }
    __syncthreads();
    size_t rowbase = (size_t)GUARD + (size_t)n * IMG_PIX + (size_t)(h + 1) * PDIM + 1;
    for (int g = tid; g < 56 * 128; g += 256) {
        int w = g >> 7, wi = g & 127;
        uint32_t val = *(const uint32_t*)(sp + w * 516 + wi * 4);
        *(uint32_t*)(g_xt8 + (rowbase + w) * XROW + wi * 4) = val;
    }
}

// ---------------- Kernel 4: int8 implicit-GEMM conv (512 thr, 4x4 warps) ----------------
__device__ __forceinline__ void mma_s8(int* c, const uint32_t* a, const uint32_t* b) {
    asm volatile(
        "mma.sync.aligned.m16n8k32.row.col.s32.s8.s8.s32 "
        "{%0,%1,%2,%3}, {%4,%5,%6,%7}, {%8,%9}, {%0,%1,%2,%3};"
        : "+r"(c[0]), "+r"(c[1]), "+r"(c[2]), "+r"(c[3])
        : "r"(a[0]), "r"(a[1]), "r"(a[2]), "r"(a[3]), "r"(b[0]), "r"(b[1]));
}
__device__ __forceinline__ void cp16(uint32_t dst, const void* src) {
    asm volatile("cp.async.cg.shared.global [%0], [%1], 16;" :: "r"(dst), "l"(src));
}

__global__ void __launch_bounds__(512, 1)
gemm_kernel(const float* __restrict__ s, const float* __restrict__ bias,
            float* __restrict__ out)
{
    extern __shared__ char sm[];
    uint32_t smb = (uint32_t)__cvta_generic_to_shared(sm);
    int tid = threadIdx.x, lane = tid & 31, wid = tid >> 5;
    int quad = lane >> 2, tq = lane & 3;
    int warp_m = wid & 3, warp_n = wid >> 2;       // 4 x 4 warps: 32x32 warp tiles
    int p0 = blockIdx.x * BN;
    int co0 = blockIdx.y * BM;

    int acc1[2][4][4], acc2[2][4][4];
    #pragma unroll
    for (int mi = 0; mi < 2; mi++)
        #pragma unroll
        for (int ni = 0; ni < 4; ni++)
            #pragma unroll
            for (int r = 0; r < 4; r++) { acc1[mi][ni][r] = 0; acc2[mi][ni][r] = 0; }

    // ---- cp.async stage loader: exactly 3 x 16B per thread ----
    auto issue = [&](int it, int st) {
        int tap = it >> 2, kc = it & 3;
        int kh = tap / 3, kw = tap - kh * 3;
        int tapoff = (kh - 1) * PDIM + (kw - 1);
        const char* asrc = g_aw8 + (size_t)co0 * AROW + tap * 256 + kc * 64;
        const char* bsrc = g_xt8 + ((size_t)(GUARD + p0 + tapoff)) * XROW + kc * 64;
        uint32_t sbase = smb + st * STAGE_BYTES;
        #pragma unroll
        for (int i = 0; i < 3; i++) {
            int g = tid + i * 512;
            int row = (g & 511) >> 2, ch = g & 3;
            if (g < 512)
                cp16(sbase + ST_A + row * SROW + ch * 16, asrc + (size_t)row * AROW + ch * 16);
            else if (g < 1024)
                cp16(sbase + ST_B1 + row * SROW + ch * 16, bsrc + (size_t)row * XROW + ch * 16);
            else
                cp16(sbase + ST_B2 + row * SROW + ch * 16, bsrc + 256 + (size_t)row * XROW + ch * 16);
        }
    };

    issue(0, 0); asm volatile("cp.async.commit_group;" ::: "memory");
    issue(1, 1); asm volatile("cp.async.commit_group;" ::: "memory");
    issue(2, 2); asm volatile("cp.async.commit_group;" ::: "memory");

    for (int it = 0; it < NITER; it++) {
        asm volatile("cp.async.wait_group 2;" ::: "memory");
        __syncthreads();
        if (it + 3 < NITER) issue(it + 3, (it + 3) & 3);
        asm volatile("cp.async.commit_group;" ::: "memory");

        char* st = sm + (it & 3) * STAGE_BYTES;
        const char* sA  = st + ST_A  + warp_m * 32 * SROW;
        const char* sB1 = st + ST_B1 + warp_n * 32 * SROW;
        const char* sB2 = st + ST_B2 + warp_n * 32 * SROW;

        #pragma unroll
        for (int ks = 0; ks < 2; ks++) {
            int col = ks * 32 + tq * 4;
            uint32_t a[2][4];
            #pragma unroll
            for (int mi = 0; mi < 2; mi++) {
                int r0 = mi * 16 + quad;
                a[mi][0] = *(const uint32_t*)(sA + r0 * SROW + col);
                a[mi][1] = *(const uint32_t*)(sA + (r0 + 8) * SROW + col);
                a[mi][2] = *(const uint32_t*)(sA + r0 * SROW + col + 16);
                a[mi][3] = *(const uint32_t*)(sA + (r0 + 8) * SROW + col + 16);
            }
            uint32_t b1[4][2], b2[4][2];
            #pragma unroll
            for (int ni = 0; ni < 4; ni++) {
                int n0 = ni * 8 + quad;
                b1[ni][0] = *(const uint32_t*)(sB1 + n0 * SROW + col);
                b1[ni][1] = *(const uint32_t*)(sB1 + n0 * SROW + col + 16);
                b2[ni][0] = *(const uint32_t*)(sB2 + n0 * SROW + col);
                b2[ni][1] = *(const uint32_t*)(sB2 + n0 * SROW + col + 16);
            }
            #pragma unroll
            for (int mi = 0; mi < 2; mi++)
                #pragma unroll
                for (int ni = 0; ni < 4; ni++) {
                    mma_s8(acc1[mi][ni], a[mi], b1[ni]);
                    mma_s8(acc2[mi][ni], a[mi], b2[ni]);
                }
        }
    }

    // ---- epilogue: combine planes, scale+bias, scatter to NCHW ----
    const float c1f = 1.0f / 127.0f;
    const float c2f = 1.0f / 32258.0f;
    #pragma unroll
    for (int mi = 0; mi < 2; mi++) {
        #pragma unroll
        for (int half = 0; half < 2; half++) {
            int co = co0 + warp_m * 32 + mi * 16 + half * 8 + quad;
            float sv = s[co], bv = bias[co];
            #pragma unroll
            for (int ni = 0; ni < 4; ni++) {
                #pragma unroll
                for (int e = 0; e < 2; e++) {
                    int ridx = half * 2 + e;
                    float f = (float)acc1[mi][ni][ridx] * c1f
                            + (float)acc2[mi][ni][ridx] * c2f;
                    float y = fmaf(f, sv, bv);
                    int q = p0 + warp_n * 32 + ni * 8 + tq * 2 + e;
                    int n = q / IMG_PIX;
                    int rem = q - n * IMG_PIX;
                    int ph = rem / PDIM, pw = rem - ph * PDIM;
                    if ((unsigned)(ph - 1) < HIMG && (unsigned)(pw - 1) < WIMG)
                        out[((size_t)n * COUTCH + co) * HWSZ + (ph - 1) * WIMG + (pw - 1)] = y;
                }
            }
        }
    }
}

// ---------------- Host ----------------
extern "C" void kernel_launch(void* const* d_in, const int* in_sizes, int n_in,
                              void* d_out, int out_size) {
    const float* x    = (const float*)d_in[0];
    const int*   wq   = (const int*)d_in[1];
    const float* s    = (const float*)d_in[2];
    const float* bias = (const float*)d_in[3];
    float* out = (float*)d_out;

    cudaFuncSetAttribute(gemm_kernel, cudaFuncAttributeMaxDynamicSharedMemorySize, SMEM_TOTAL);

    prep_w_kernel<<<(9 * 256 * 256 + 255) / 256, 256>>>(wq);
    {
        const long long zt = (long long)(128 + NIMG * 228) * 32;
        zero_xt_kernel<<<(int)((zt + 255) / 256), 256>>>();
    }
    prep_x_kernel<<<NIMG * HIMG, 256>>>(x);
    gemm_kernel<<<dim3(NTILES, 2), 512, SMEM_TOTAL>>>(s, bias, out);
}

// round 7
// speedup vs baseline: 1.1699x; 1.1699x over previous
#include <cuda_runtime.h>
#include <cstdint>

#define NIMG   32
#define CINCH  256
#define COUTCH 256
#define HIMG   56
#define WIMG   56
#define HWSZ   (HIMG*WIMG)           // 3136
#define PDIM   58
#define IMG_PIX (PDIM*PDIM)          // 3364
#define PIX    (NIMG*IMG_PIX)        // 107648 = 841*128
#define GUARD  64
#define TOT_ROWS (GUARD + PIX + GUARD)
#define XROW   512                   // bytes per X_t row: [a1:256 | a2:256]
#define AROW   2304                  // bytes per weight row (9*256)
#define NTILES 841                   // PIX / 128

#define BM 128
#define BN 128
#define NITER 18                     // 9 taps * 2 chunks of 128
#define SROW 144                     // padded smem row stride (conflict-free for ldmatrix)
#define ST_A  0
#define ST_B1 (128*SROW)             // 18432
#define ST_B2 (2*128*SROW)           // 36864
#define STAGE_BYTES (3*128*SROW)     // 55296
#define SMEM_TOTAL (3*STAGE_BYTES)   // 165888

__device__ __align__(256) char g_xt8[(size_t)TOT_ROWS * XROW];   // ~55.4 MB
__device__ __align__(256) char g_aw8[(size_t)COUTCH * AROW];     // ~590 KB

// ---------------- Kernel 1: weight prep (int32 ternary -> int8, [co][tap*256+ci]) ----------------
__global__ void prep_w_kernel(const int* __restrict__ wq) {
    int t = blockIdx.x * 256 + threadIdx.x;
    if (t >= 9 * 256 * 256) return;
    int ci = t & 255, co = (t >> 8) & 255, tap = t >> 16;
    g_aw8[(size_t)co * AROW + tap * 256 + ci] = (char)wq[(co * 256 + ci) * 9 + tap];
}

// ---------------- Kernel 2: zero guards + padded-border rows of X_t ----------------
__global__ void zero_xt_kernel() {
    const int NROWS = 128 + NIMG * 228;      // 7424
    long long t = (long long)blockIdx.x * blockDim.x + threadIdx.x;
    if (t >= (long long)NROWS * 32) return;  // 32 uint4 per row
    int r = (int)(t >> 5), c = (int)(t & 31);
    size_t row;
    if (r < 64) row = (size_t)r;                               // front guard
    else if (r < 128) row = (size_t)GUARD + PIX + (r - 64);    // back guard
    else {
        int rb = r - 128, n = rb / 228, b = rb % 228;
        int ph, pw;
        if (b < 58)        { ph = 0;           pw = b; }
        else if (b < 116)  { ph = 57;          pw = b - 58; }
        else if (b < 172)  { ph = b - 116 + 1; pw = 0; }
        else               { ph = b - 172 + 1; pw = 57; }
        row = (size_t)GUARD + (size_t)n * IMG_PIX + (size_t)ph * PDIM + pw;
    }
    ((uint4*)g_xt8)[row * 32 + c] = make_uint4(0, 0, 0, 0);
}

// ---------------- Kernel 3: activation prep (clamp + 2-level int8 + transpose) ----------------
__global__ void __launch_bounds__(256) prep_x_kernel(const float* __restrict__ x) {
    __shared__ char sp[56 * 516];
    int nh = blockIdx.x;
    int n = nh / HIMG, h = nh % HIMG;
    int tid = threadIdx.x;
    const float c1f = 1.0f / 127.0f;
    for (int idx = tid; idx < 256 * WIMG; idx += 256) {
        int ci = idx / WIMG, w = idx - ci * WIMG;
        float v = x[(((size_t)n * CINCH + ci) * HIMG + h) * WIMG + w];
        v = fminf(fmaxf(v, -1.0f), 1.0f);
        int a1 = __float2int_rn(v * 127.0f);
        float r = fmaf((float)a1, -c1f, v);
        int a2 = __float2int_rn(r * 32258.0f);
        a2 = max(-127, min(127, a2));
        sp[w * 516 + ci]       = (char)a1;
        sp[w * 516 + 256 + ci] = (char)a2;
    }
    __syncthreads();
    size_t rowbase = (size_t)GUARD + (size_t)n * IMG_PIX + (size_t)(h + 1) * PDIM + 1;
    for (int g = tid; g < 56 * 128; g += 256) {
        int w = g >> 7, wi = g & 127;
        uint32_t val = *(const uint32_t*)(sp + w * 516 + wi * 4);
        *(uint32_t*)(g_xt8 + (rowbase + w) * XROW + wi * 4) = val;
    }
}

// ---------------- Kernel 4: int8 implicit-GEMM conv (512 thr, 4x4 warps, BK=128, ldmatrix) ----------------
__device__ __forceinline__ void mma_s8(int* c, const uint32_t* a, const uint32_t* b) {
    asm volatile(
        "mma.sync.aligned.m16n8k32.row.col.s32.s8.s8.s32 "
        "{%0,%1,%2,%3}, {%4,%5,%6,%7}, {%8,%9}, {%0,%1,%2,%3};"
        : "+r"(c[0]), "+r"(c[1]), "+r"(c[2]), "+r"(c[3])
        : "r"(a[0]), "r"(a[1]), "r"(a[2]), "r"(a[3]), "r"(b[0]), "r"(b[1]));
}
__device__ __forceinline__ void cp16(uint32_t dst, const void* src) {
    asm volatile("cp.async.cg.shared.global [%0], [%1], 16;" :: "r"(dst), "l"(src));
}
__device__ __forceinline__ void ldm_x4(uint32_t* r, uint32_t addr) {
    asm volatile("ldmatrix.sync.aligned.m8n8.x4.shared.b16 {%0,%1,%2,%3}, [%4];"
        : "=r"(r[0]), "=r"(r[1]), "=r"(r[2]), "=r"(r[3]) : "r"(addr));
}

__global__ void __launch_bounds__(512, 1)
gemm_kernel(const float* __restrict__ s, const float* __restrict__ bias,
            float* __restrict__ out)
{
    extern __shared__ char sm[];
    uint32_t smb = (uint32_t)__cvta_generic_to_shared(sm);
    int tid = threadIdx.x, lane = tid & 31, wid = tid >> 5;
    int quad = lane >> 2, tq = lane & 3;
    int warp_m = wid & 3, warp_n = wid >> 2;       // 4 x 4 warps: 32x32 warp tiles
    int p0 = blockIdx.x * BN;
    int co0 = blockIdx.y * BM;

    // ldmatrix per-lane offset: lanes 0-7 -> rows 0-7 (k-half 0), 8-15 -> rows 8-15 (h0),
    // 16-23 -> rows 0-7 (h1), 24-31 -> rows 8-15 (h1)
    int lg = lane >> 3, lr = lane & 7;
    uint32_t laneoff = (uint32_t)(((lg & 1) * 8 + lr) * SROW + (lg >> 1) * 16);
    uint32_t a_base  = (uint32_t)(ST_A  + warp_m * 32 * SROW) + laneoff;
    uint32_t b1_base = (uint32_t)(ST_B1 + warp_n * 32 * SROW) + laneoff;
    uint32_t b2_base = (uint32_t)(ST_B2 + warp_n * 32 * SROW) + laneoff;

    int acc1[2][4][4], acc2[2][4][4];
    #pragma unroll
    for (int mi = 0; mi < 2; mi++)
        #pragma unroll
        for (int ni = 0; ni < 4; ni++)
            #pragma unroll
            for (int r = 0; r < 4; r++) { acc1[mi][ni][r] = 0; acc2[mi][ni][r] = 0; }

    // ---- cp.async stage loader: exactly 6 x 16B per thread (stage = 48KB data) ----
    auto issue = [&](int it, int st) {
        int tap = it >> 1, kc = it & 1;
        int kh = tap / 3, kw = tap - kh * 3;
        int tapoff = (kh - 1) * PDIM + (kw - 1);
        const char* asrc = g_aw8 + (size_t)co0 * AROW + tap * 256 + kc * 128;
        const char* bsrc = g_xt8 + ((size_t)(GUARD + p0 + tapoff)) * XROW + kc * 128;
        uint32_t sbase = smb + st * STAGE_BYTES;
        #pragma unroll
        for (int i = 0; i < 6; i++) {
            int g = tid + i * 512;                 // 0..3071
            int row = (g & 1023) >> 3, ch = g & 7; // 128 rows x 8 chunks of 16B
            if (g < 1024)
                cp16(sbase + ST_A + row * SROW + ch * 16, asrc + (size_t)row * AROW + ch * 16);
            else if (g < 2048)
                cp16(sbase + ST_B1 + row * SROW + ch * 16, bsrc + (size_t)row * XROW + ch * 16);
            else
                cp16(sbase + ST_B2 + row * SROW + ch * 16, bsrc + 256 + (size_t)row * XROW + ch * 16);
        }
    };

    issue(0, 0); asm volatile("cp.async.commit_group;" ::: "memory");
    issue(1, 1); asm volatile("cp.async.commit_group;" ::: "memory");

    for (int it = 0; it < NITER; it++) {
        asm volatile("cp.async.wait_group 1;" ::: "memory");
        __syncthreads();
        if (it + 2 < NITER) issue(it + 2, (it + 2) % 3);
        asm volatile("cp.async.commit_group;" ::: "memory");

        uint32_t stb = smb + (it % 3) * STAGE_BYTES;
        uint32_t sa = stb + a_base, s1 = stb + b1_base, s2 = stb + b2_base;

        #pragma unroll
        for (int ks = 0; ks < 4; ks++) {
            uint32_t kof = ks * 32;
            uint32_t a[2][4], b1[4][2], b2[4][2];
            // A: 2 x ldmatrix.x4 -> a[mi][0..3] (rows0-7 h0, rows8-15 h0, rows0-7 h1, rows8-15 h1)
            ldm_x4(a[0], sa + kof);
            ldm_x4(a[1], sa + 16 * SROW + kof);
            // B: 2 ni per x4: regs = (cols0-7 h0, cols8-15 h0, cols0-7 h1, cols8-15 h1)
            uint32_t t0[4], t1[4], t2[4], t3[4];
            ldm_x4(t0, s1 + kof);
            ldm_x4(t1, s1 + 16 * SROW + kof);
            ldm_x4(t2, s2 + kof);
            ldm_x4(t3, s2 + 16 * SROW + kof);
            b1[0][0] = t0[0]; b1[1][0] = t0[1]; b1[0][1] = t0[2]; b1[1][1] = t0[3];
            b1[2][0] = t1[0]; b1[3][0] = t1[1]; b1[2][1] = t1[2]; b1[3][1] = t1[3];
            b2[0][0] = t2[0]; b2[1][0] = t2[1]; b2[0][1] = t2[2]; b2[1][1] = t2[3];
            b2[2][0] = t3[0]; b2[3][0] = t3[1]; b2[2][1] = t3[2]; b2[3][1] = t3[3];
            #pragma unroll
            for (int mi = 0; mi < 2; mi++)
                #pragma unroll
                for (int ni = 0; ni < 4; ni++) {
                    mma_s8(acc1[mi][ni], a[mi], b1[ni]);
                    mma_s8(acc2[mi][ni], a[mi], b2[ni]);
                }
        }
    }

    // ---- epilogue: combine planes, scale+bias, scatter to NCHW ----
    const float c1f = 1.0f / 127.0f;
    const float c2f = 1.0f / 32258.0f;
    #pragma unroll
    for (int mi = 0; mi < 2; mi++) {
        #pragma unroll
        for (int half = 0; half < 2; half++) {
            int co = co0 + warp_m * 32 + mi * 16 + half * 8 + quad;
            float sv = s[co], bv = bias[co];
            #pragma unroll
            for (int ni = 0; ni < 4; ni++) {
                #pragma unroll
                for (int e = 0; e < 2; e++) {
                    int ridx = half * 2 + e;
                    float f = (float)acc1[mi][ni][ridx] * c1f
                            + (float)acc2[mi][ni][ridx] * c2f;
                    float y = fmaf(f, sv, bv);
                    int q = p0 + warp_n * 32 + ni * 8 + tq * 2 + e;
                    int n = q / IMG_PIX;
                    int rem = q - n * IMG_PIX;
                    int ph = rem / PDIM, pw = rem - ph * PDIM;
                    if ((unsigned)(ph - 1) < HIMG && (unsigned)(pw - 1) < WIMG)
                        out[((size_t)n * COUTCH + co) * HWSZ + (ph - 1) * WIMG + (pw - 1)] = y;
                }
            }
        }
    }
}

// ---------------- Host ----------------
extern "C" void kernel_launch(void* const* d_in, const int* in_sizes, int n_in,
                              void* d_out, int out_size) {
    const float* x    = (const float*)d_in[0];
    const int*   wq   = (const int*)d_in[1];
    const float* s    = (const float*)d_in[2];
    const float* bias = (const float*)d_in[3];
    float* out = (float*)d_out;

    cudaFuncSetAttribute(gemm_kernel, cudaFuncAttributeMaxDynamicSharedMemorySize, SMEM_TOTAL);

    prep_w_kernel<<<(9 * 256 * 256 + 255) / 256, 256>>>(wq);
    {
        const long long zt = (long long)(128 + NIMG * 228) * 32;
        zero_xt_kernel<<<(int)((zt + 255) / 256), 256>>>();
    }
    prep_x_kernel<<<NIMG * HIMG, 256>>>(x);
    gemm_kernel<<<dim3(NTILES, 2), 512, SMEM_TOTAL>>>(s, bias, out);
}

// round 10
// speedup vs baseline: 1.3537x; 1.1571x over previous
#include <cuda_runtime.h>
#include <cstdint>

#define NIMG   32
#define CINCH  256
#define COUTCH 256
#define HIMG   56
#define WIMG   56
#define HWSZ   (HIMG*WIMG)           // 3136
#define PDIM   58
#define IMG_PIX (PDIM*PDIM)          // 3364
#define PIX    (NIMG*IMG_PIX)        // 107648
#define GUARD  64
#define TOT_ROWS (GUARD + PIX + GUARD)
#define XROW   512                   // bytes per X_t row: [a1:256 | a2:256]
#define AROW   2304                  // bytes per weight row (9*256)
#define NTILES_B 1682                // PIX / 64

#define BM 128
#define BN 64
#define NITER 18                     // 9 taps * 2 chunks of 128
#define SROW 144                     // padded smem row stride (ldmatrix conflict-free)
#define ST_A  0
#define ST_B1 (128*SROW)             // 18432
#define ST_B2 (ST_B1 + 64*SROW)      // 27648
#define STAGE_BYTES (ST_B2 + 64*SROW)   // 36864
#define SMEM_TOTAL (3*STAGE_BYTES)   // 110592

// fused prep block ranges
#define PXBLK (NIMG*HIMG)            // 1792
#define ZBLK  928                    // 7424 rows * 32 uint4 / 256
#define WBLK  2304                   // 589824 / 256
#define PREP_BLOCKS (PXBLK + ZBLK + WBLK)

__device__ __align__(256) char g_xt8[(size_t)TOT_ROWS * XROW];   // ~55.4 MB
__device__ __align__(256) char g_aw8[(size_t)COUTCH * AROW];     // ~590 KB

// ---------------- Fused prep kernel: prep_x | zero borders | prep_w ----------------
__global__ void __launch_bounds__(256) prep_all_kernel(const float* __restrict__ x,
                                                       const int* __restrict__ wq) {
    int b = blockIdx.x;
    int tid = threadIdx.x;
    if (b < PXBLK) {
        // ---- activation prep: clamp + 2-level int8 + transpose ----
        __shared__ char sp[56 * 516];
        int n = b / HIMG, h = b % HIMG;
        const float c1f = 1.0f / 127.0f;
        for (int idx = tid; idx < 256 * WIMG; idx += 256) {
            int ci = idx / WIMG, w = idx - ci * WIMG;
            float v = x[(((size_t)n * CINCH + ci) * HIMG + h) * WIMG + w];
            v = fminf(fmaxf(v, -1.0f), 1.0f);
            int a1 = __float2int_rn(v * 127.0f);
            float r = fmaf((float)a1, -c1f, v);
            int a2 = __float2int_rn(r * 32258.0f);
            a2 = max(-127, min(127, a2));
            sp[w * 516 + ci]       = (char)a1;
            sp[w * 516 + 256 + ci] = (char)a2;
        }
        __syncthreads();
        size_t rowbase = (size_t)GUARD + (size_t)n * IMG_PIX + (size_t)(h + 1) * PDIM + 1;
        for (int g = tid; g < 56 * 128; g += 256) {
            int w = g >> 7, wi = g & 127;
            uint32_t val = *(const uint32_t*)(sp + w * 516 + wi * 4);
            *(uint32_t*)(g_xt8 + (rowbase + w) * XROW + wi * 4) = val;
        }
    } else if (b < PXBLK + ZBLK) {
        // ---- zero guards + padded-border rows ----
        int t = (b - PXBLK) * 256 + tid;          // < 237568 = 7424*32
        int r = t >> 5, c = t & 31;
        size_t row;
        if (r < 64) row = (size_t)r;
        else if (r < 128) row = (size_t)GUARD + PIX + (r - 64);
        else {
            int rb = r - 128, n = rb / 228, bb = rb % 228;
            int ph, pw;
            if (bb < 58)        { ph = 0;            pw = bb; }
            else if (bb < 116)  { ph = 57;           pw = bb - 58; }
            else if (bb < 172)  { ph = bb - 116 + 1; pw = 0; }
            else                { ph = bb - 172 + 1; pw = 57; }
            row = (size_t)GUARD + (size_t)n * IMG_PIX + (size_t)ph * PDIM + pw;
        }
        ((uint4*)g_xt8)[row * 32 + c] = make_uint4(0, 0, 0, 0);
    } else {
        // ---- weight prep: int32 ternary -> int8, [co][tap*256+ci] ----
        int t = (b - PXBLK - ZBLK) * 256 + tid;   // < 589824
        int ci = t & 255, co = (t >> 8) & 255, tap = t >> 16;
        g_aw8[(size_t)co * AROW + tap * 256 + ci] = (char)wq[(co * 256 + ci) * 9 + tap];
    }
}

// ---------------- GEMM: int8 implicit conv, 256 thr, 4x2 warps, 2 CTAs/SM ----------------
__device__ __forceinline__ void mma_s8(int* c, const uint32_t* a, const uint32_t* b) {
    asm volatile(
        "mma.sync.aligned.m16n8k32.row.col.s32.s8.s8.s32 "
        "{%0,%1,%2,%3}, {%4,%5,%6,%7}, {%8,%9}, {%0,%1,%2,%3};"
        : "+r"(c[0]), "+r"(c[1]), "+r"(c[2]), "+r"(c[3])
        : "r"(a[0]), "r"(a[1]), "r"(a[2]), "r"(a[3]), "r"(b[0]), "r"(b[1]));
}
__device__ __forceinline__ void cp16(uint32_t dst, const void* src) {
    asm volatile("cp.async.cg.shared.global [%0], [%1], 16;" :: "r"(dst), "l"(src));
}
__device__ __forceinline__ void ldm_x4(uint32_t* r, uint32_t addr) {
    asm volatile("ldmatrix.sync.aligned.m8n8.x4.shared.b16 {%0,%1,%2,%3}, [%4];"
        : "=r"(r[0]), "=r"(r[1]), "=r"(r[2]), "=r"(r[3]) : "r"(addr));
}

__global__ void __launch_bounds__(256, 2)
gemm_kernel(const float* __restrict__ s, const float* __restrict__ bias,
            float* __restrict__ out)
{
    extern __shared__ char sm[];
    uint32_t smb = (uint32_t)__cvta_generic_to_shared(sm);
    int tid = threadIdx.x, lane = tid & 31, wid = tid >> 5;
    int quad = lane >> 2, tq = lane & 3;
    int warp_m = wid & 3, warp_n = wid >> 2;       // 4 x 2 warps: 32x32 warp tiles
    int p0 = blockIdx.x * BN;
    int co0 = blockIdx.y * BM;

    int lg = lane >> 3, lr = lane & 7;
    uint32_t laneoff = (uint32_t)(((lg & 1) * 8 + lr) * SROW + (lg >> 1) * 16);
    uint32_t a_base  = (uint32_t)(ST_A  + warp_m * 32 * SROW) + laneoff;
    uint32_t b1_base = (uint32_t)(ST_B1 + warp_n * 32 * SROW) + laneoff;
    uint32_t b2_base = (uint32_t)(ST_B2 + warp_n * 32 * SROW) + laneoff;

    int acc1[2][4][4], acc2[2][4][4];
    #pragma unroll
    for (int mi = 0; mi < 2; mi++)
        #pragma unroll
        for (int ni = 0; ni < 4; ni++)
            #pragma unroll
            for (int r = 0; r < 4; r++) { acc1[mi][ni][r] = 0; acc2[mi][ni][r] = 0; }

    // ---- cp.async stage loader: 8 x 16B per thread (stage = 32KB data) ----
    auto issue = [&](int it, int st) {
        int tap = it >> 1, kc = it & 1;
        int kh = tap / 3, kw = tap - kh * 3;
        int tapoff = (kh - 1) * PDIM + (kw - 1);
        const char* asrc = g_aw8 + (size_t)co0 * AROW + tap * 256 + kc * 128;
        const char* bsrc = g_xt8 + ((size_t)(GUARD + p0 + tapoff)) * XROW + kc * 128;
        uint32_t sbase = smb + st * STAGE_BYTES;
        #pragma unroll
        for (int i = 0; i < 8; i++) {
            int g = tid + i * 256;                 // 0..2047
            if (g < 1024) {
                int row = g >> 3, ch = g & 7;      // A: 128 rows x 8 chunks
                cp16(sbase + ST_A + row * SROW + ch * 16, asrc + (size_t)row * AROW + ch * 16);
            } else if (g < 1536) {
                int row = (g - 1024) >> 3, ch = g & 7;  // B1: 64 rows x 8 chunks
                cp16(sbase + ST_B1 + row * SROW + ch * 16, bsrc + (size_t)row * XROW + ch * 16);
            } else {
                int row = (g - 1536) >> 3, ch = g & 7;  // B2: 64 rows x 8 chunks
                cp16(sbase + ST_B2 + row * SROW + ch * 16, bsrc + 256 + (size_t)row * XROW + ch * 16);
            }
        }
    };

    issue(0, 0); asm volatile("cp.async.commit_group;" ::: "memory");
    issue(1, 1); asm volatile("cp.async.commit_group;" ::: "memory");

    for (int it = 0; it < NITER; it++) {
        asm volatile("cp.async.wait_group 1;" ::: "memory");
        __syncthreads();
        if (it + 2 < NITER) issue(it + 2, (it + 2) % 3);
        asm volatile("cp.async.commit_group;" ::: "memory");

        uint32_t stb = smb + (it % 3) * STAGE_BYTES;
        uint32_t sa = stb + a_base, s1 = stb + b1_base, s2 = stb + b2_base;

        #pragma unroll
        for (int ks = 0; ks < 4; ks++) {
            uint32_t kof = ks * 32;
            uint32_t a[2][4], b1[4][2], b2[4][2];
            ldm_x4(a[0], sa + kof);
            ldm_x4(a[1], sa + 16 * SROW + kof);
            uint32_t t0[4], t1[4], t2[4], t3[4];
            ldm_x4(t0, s1 + kof);
            ldm_x4(t1, s1 + 16 * SROW + kof);
            ldm_x4(t2, s2 + kof);
            ldm_x4(t3, s2 + 16 * SROW + kof);
            b1[0][0] = t0[0]; b1[1][0] = t0[1]; b1[0][1] = t0[2]; b1[1][1] = t0[3];
            b1[2][0] = t1[0]; b1[3][0] = t1[1]; b1[2][1] = t1[2]; b1[3][1] = t1[3];
            b2[0][0] = t2[0]; b2[1][0] = t2[1]; b2[0][1] = t2[2]; b2[1][1] = t2[3];
            b2[2][0] = t3[0]; b2[3][0] = t3[1]; b2[2][1] = t3[2]; b2[3][1] = t3[3];
            #pragma unroll
            for (int mi = 0; mi < 2; mi++)
                #pragma unroll
                for (int ni = 0; ni < 4; ni++) {
                    mma_s8(acc1[mi][ni], a[mi], b1[ni]);
                    mma_s8(acc2[mi][ni], a[mi], b2[ni]);
                }
        }
    }

    // ---- epilogue: combine planes, scale+bias, scatter to NCHW ----
    const float c1f = 1.0f / 127.0f;
    const float c2f = 1.0f / 32258.0f;
    #pragma unroll
    for (int mi = 0; mi < 2; mi++) {
        #pragma unroll
        for (int half = 0; half < 2; half++) {
            int co = co0 + warp_m * 32 + mi * 16 + half * 8 + quad;
            float sv = s[co], bv = bias[co];
            #pragma unroll
            for (int ni = 0; ni < 4; ni++) {
                #pragma unroll
                for (int e = 0; e < 2; e++) {
                    int ridx = half * 2 + e;
                    float f = (float)acc1[mi][ni][ridx] * c1f
                            + (float)acc2[mi][ni][ridx] * c2f;
                    float y = fmaf(f, sv, bv);
                    int q = p0 + warp_n * 32 + ni * 8 + tq * 2 + e;
                    int n = q / IMG_PIX;
                    int rem = q - n * IMG_PIX;
                    int ph = rem / PDIM, pw = rem - ph * PDIM;
                    if ((unsigned)(ph - 1) < HIMG && (unsigned)(pw - 1) < WIMG)
                        out[((size_t)n * COUTCH + co) * HWSZ + (ph - 1) * WIMG + (pw - 1)] = y;
                }
            }
        }
    }
}

// ---------------- Host ----------------
extern "C" void kernel_launch(void* const* d_in, const int* in_sizes, int n_in,
                              void* d_out, int out_size) {
    const float* x    = (const float*)d_in[0];
    const int*   wq   = (const int*)d_in[1];
    const float* s    = (const float*)d_in[2];
    const float* bias = (const float*)d_in[3];
    float* out = (float*)d_out;

    cudaFuncSetAttribute(gemm_kernel, cudaFuncAttributeMaxDynamicSharedMemorySize, SMEM_TOTAL);

    prep_all_kernel<<<PREP_BLOCKS, 256>>>(x, wq);
    gemm_kernel<<<dim3(NTILES_B, 2), 256, SMEM_TOTAL>>>(s, bias, out);
}

// round 14
// speedup vs baseline: 1.4076x; 1.0398x over previous
#include <cuda_runtime.h>
#include <cstdint>

#define NIMG   32
#define CINCH  256
#define COUTCH 256
#define HIMG   56
#define WIMG   56
#define HWSZ   (HIMG*WIMG)           // 3136
#define PDIM   58
#define IMG_PIX (PDIM*PDIM)          // 3364
#define PIX    (NIMG*IMG_PIX)        // 107648
#define GUARD  64
#define TOT_ROWS (GUARD + PIX + GUARD)
#define XROW   512                   // bytes per X_t row: [a1:256 | a2:256]
#define AROW   2304                  // bytes per weight row (9*256)
#define NTILES_B 1682                // PIX / 64

#define BM 128
#define BN 64
#define NITER 18                     // 9 taps * 2 chunks of 128
#define SROW 144                     // padded smem row stride (ldmatrix conflict-free)
#define ST_A  0
#define ST_B1 (128*SROW)             // 18432
#define ST_B2 (ST_B1 + 64*SROW)      // 27648
#define STAGE_BYTES (ST_B2 + 64*SROW)   // 36864
#define SMEM_TOTAL (3*STAGE_BYTES)   // 110592

// fused prep block ranges
#define PXBLK (NIMG*HIMG)            // 1792
#define ZBLK  928                    // 7424 rows * 32 uint4 / 256
#define WBLK  2304                   // 589824 / 256
#define PREP_BLOCKS (PXBLK + ZBLK + WBLK)

__device__ __align__(256) char g_xt8[(size_t)TOT_ROWS * XROW];   // ~55.4 MB
__device__ __align__(256) char g_aw8[(size_t)COUTCH * AROW];     // ~590 KB

// ---------------- Fused prep kernel: prep_x | zero borders | prep_w ----------------
__global__ void __launch_bounds__(256) prep_all_kernel(const float* __restrict__ x,
                                                       const int* __restrict__ wq) {
    int b = blockIdx.x;
    int tid = threadIdx.x;
    if (b < PXBLK) {
        // ---- activation prep: clamp + 2-level int8 + transpose ----
        __shared__ char sp[56 * 516];
        int n = b / HIMG, h = b % HIMG;
        const float c1f = 1.0f / 127.0f;
        for (int idx = tid; idx < 256 * WIMG; idx += 256) {
            int ci = idx / WIMG, w = idx - ci * WIMG;
            float v = x[(((size_t)n * CINCH + ci) * HIMG + h) * WIMG + w];
            v = fminf(fmaxf(v, -1.0f), 1.0f);
            int a1 = __float2int_rn(v * 127.0f);
            float r = fmaf((float)a1, -c1f, v);
            int a2 = __float2int_rn(r * 32258.0f);
            a2 = max(-127, min(127, a2));
            sp[w * 516 + ci]       = (char)a1;
            sp[w * 516 + 256 + ci] = (char)a2;
        }
        __syncthreads();
        size_t rowbase = (size_t)GUARD + (size_t)n * IMG_PIX + (size_t)(h + 1) * PDIM + 1;
        for (int g = tid; g < 56 * 128; g += 256) {
            int w = g >> 7, wi = g & 127;
            uint32_t val = *(const uint32_t*)(sp + w * 516 + wi * 4);
            *(uint32_t*)(g_xt8 + (rowbase + w) * XROW + wi * 4) = val;
        }
    } else if (b < PXBLK + ZBLK) {
        // ---- zero guards + padded-border rows ----
        int t = (b - PXBLK) * 256 + tid;          // < 237568 = 7424*32
        int r = t >> 5, c = t & 31;
        size_t row;
        if (r < 64) row = (size_t)r;
        else if (r < 128) row = (size_t)GUARD + PIX + (r - 64);
        else {
            int rb = r - 128, n = rb / 228, bb = rb % 228;
            int ph, pw;
            if (bb < 58)        { ph = 0;            pw = bb; }
            else if (bb < 116)  { ph = 57;           pw = bb - 58; }
            else if (bb < 172)  { ph = bb - 116 + 1; pw = 0; }
            else                { ph = bb - 172 + 1; pw = 57; }
            row = (size_t)GUARD + (size_t)n * IMG_PIX + (size_t)ph * PDIM + pw;
        }
        ((uint4*)g_xt8)[row * 32 + c] = make_uint4(0, 0, 0, 0);
    } else {
        // ---- weight prep: int32 ternary -> int8, [co][tap*256+ci] ----
        int t = (b - PXBLK - ZBLK) * 256 + tid;   // < 589824
        int ci = t & 255, co = (t >> 8) & 255, tap = t >> 16;
        g_aw8[(size_t)co * AROW + tap * 256 + ci] = (char)wq[(co * 256 + ci) * 9 + tap];
    }
}

// ---------------- GEMM: int8 implicit conv, 256 thr, 4x2 warps, 2 CTAs/SM ----------------
__device__ __forceinline__ void mma_s8b(int* c, const uint32_t* a, uint32_t b0, uint32_t b1) {
    asm volatile(
        "mma.sync.aligned.m16n8k32.row.col.s32.s8.s8.s32 "
        "{%0,%1,%2,%3}, {%4,%5,%6,%7}, {%8,%9}, {%0,%1,%2,%3};"
        : "+r"(c[0]), "+r"(c[1]), "+r"(c[2]), "+r"(c[3])
        : "r"(a[0]), "r"(a[1]), "r"(a[2]), "r"(a[3]), "r"(b0), "r"(b1));
}
__device__ __forceinline__ void cp16(uint32_t dst, const void* src) {
    asm volatile("cp.async.cg.shared.global [%0], [%1], 16;" :: "r"(dst), "l"(src));
}
__device__ __forceinline__ void ldm_x4(uint32_t* r, uint32_t addr) {
    asm volatile("ldmatrix.sync.aligned.m8n8.x4.shared.b16 {%0,%1,%2,%3}, [%4];"
        : "=r"(r[0]), "=r"(r[1]), "=r"(r[2]), "=r"(r[3]) : "r"(addr));
}

__global__ void __launch_bounds__(256, 2)
gemm_kernel(const float* __restrict__ s, const float* __restrict__ bias,
            float* __restrict__ out)
{
    extern __shared__ char sm[];
    uint32_t smb = (uint32_t)__cvta_generic_to_shared(sm);
    int tid = threadIdx.x, lane = tid & 31, wid = tid >> 5;
    int quad = lane >> 2, tq = lane & 3;
    int warp_m = wid & 3, warp_n = wid >> 2;       // 4 x 2 warps: 32x32 warp tiles
    int p0 = blockIdx.x * BN;
    int co0 = blockIdx.y * BM;

    int lg = lane >> 3, lr = lane & 7;
    uint32_t laneoff = (uint32_t)(((lg & 1) * 8 + lr) * SROW + (lg >> 1) * 16);
    uint32_t a_base  = (uint32_t)(ST_A  + warp_m * 32 * SROW) + laneoff;
    uint32_t b1_base = (uint32_t)(ST_B1 + warp_n * 32 * SROW) + laneoff;
    uint32_t b2_base = (uint32_t)(ST_B2 + warp_n * 32 * SROW) + laneoff;

    int acc1[2][4][4], acc2[2][4][4];
    #pragma unroll
    for (int mi = 0; mi < 2; mi++)
        #pragma unroll
        for (int ni = 0; ni < 4; ni++)
            #pragma unroll
            for (int r = 0; r < 4; r++) { acc1[mi][ni][r] = 0; acc2[mi][ni][r] = 0; }

    // ---- cp.async stage loader: 8 x 16B per thread (stage = 32KB data) ----
    auto issue = [&](int it, int st) {
        int tap = it >> 1, kc = it & 1;
        int kh = tap / 3, kw = tap - kh * 3;
        int tapoff = (kh - 1) * PDIM + (kw - 1);
        const char* asrc = g_aw8 + (size_t)co0 * AROW + tap * 256 + kc * 128;
        const char* bsrc = g_xt8 + ((size_t)(GUARD + p0 + tapoff)) * XROW + kc * 128;
        uint32_t sbase = smb + st * STAGE_BYTES;
        #pragma unroll
        for (int i = 0; i < 8; i++) {
            int g = tid + i * 256;                 // 0..2047
            if (g < 1024) {
                int row = g >> 3, ch = g & 7;      // A: 128 rows x 8 chunks
                cp16(sbase + ST_A + row * SROW + ch * 16, asrc + (size_t)row * AROW + ch * 16);
            } else if (g < 1536) {
                int row = (g - 1024) >> 3, ch = g & 7;  // B1: 64 rows x 8 chunks
                cp16(sbase + ST_B1 + row * SROW + ch * 16, bsrc + (size_t)row * XROW + ch * 16);
            } else {
                int row = (g - 1536) >> 3, ch = g & 7;  // B2: 64 rows x 8 chunks
                cp16(sbase + ST_B2 + row * SROW + ch * 16, bsrc + 256 + (size_t)row * XROW + ch * 16);
            }
        }
    };

    issue(0, 0); asm volatile("cp.async.commit_group;" ::: "memory");
    issue(1, 1); asm volatile("cp.async.commit_group;" ::: "memory");

    for (int it = 0; it < NITER; it++) {
        asm volatile("cp.async.wait_group 1;" ::: "memory");
        __syncthreads();

        uint32_t stb = smb + (it % 3) * STAGE_BYTES;
        uint32_t sa = stb + a_base, s1 = stb + b1_base, s2 = stb + b2_base;

        // double-buffered fragments: prefetch ks+1 while ks's MMAs run
        uint32_t af[2][2][4], bf[2][4][4];

        // prefetch ks = 0
        ldm_x4(af[0][0], sa);
        ldm_x4(af[0][1], sa + 16 * SROW);
        ldm_x4(bf[0][0], s1);
        ldm_x4(bf[0][1], s1 + 16 * SROW);
        ldm_x4(bf[0][2], s2);
        ldm_x4(bf[0][3], s2 + 16 * SROW);

        // next-stage global->smem copies overlap with fragment latency + MMAs
        if (it + 2 < NITER) issue(it + 2, (it + 2) % 3);
        asm volatile("cp.async.commit_group;" ::: "memory");

        #pragma unroll
        for (int ks = 0; ks < 4; ks++) {
            const int c = ks & 1, nx = c ^ 1;
            if (ks < 3) {
                uint32_t kof = (uint32_t)(ks + 1) * 32;
                ldm_x4(af[nx][0], sa + kof);
                ldm_x4(af[nx][1], sa + 16 * SROW + kof);
                ldm_x4(bf[nx][0], s1 + kof);
                ldm_x4(bf[nx][1], s1 + 16 * SROW + kof);
                ldm_x4(bf[nx][2], s2 + kof);
                ldm_x4(bf[nx][3], s2 + 16 * SROW + kof);
            }
            #pragma unroll
            for (int mi = 0; mi < 2; mi++) {
                mma_s8b(acc1[mi][0], af[c][mi], bf[c][0][0], bf[c][0][2]);
                mma_s8b(acc1[mi][1], af[c][mi], bf[c][0][1], bf[c][0][3]);
                mma_s8b(acc1[mi][2], af[c][mi], bf[c][1][0], bf[c][1][2]);
                mma_s8b(acc1[mi][3], af[c][mi], bf[c][1][1], bf[c][1][3]);
                mma_s8b(acc2[mi][0], af[c][mi], bf[c][2][0], bf[c][2][2]);
                mma_s8b(acc2[mi][1], af[c][mi], bf[c][2][1], bf[c][2][3]);
                mma_s8b(acc2[mi][2], af[c][mi], bf[c][3][0], bf[c][3][2]);
                mma_s8b(acc2[mi][3], af[c][mi], bf[c][3][1], bf[c][3][3]);
            }
        }
    }

    // ---- epilogue: combine planes, scale+bias, scatter to NCHW ----
    const float c1f = 1.0f / 127.0f;
    const float c2f = 1.0f / 32258.0f;
    #pragma unroll
    for (int mi = 0; mi < 2; mi++) {
        #pragma unroll
        for (int half = 0; half < 2; half++) {
            int co = co0 + warp_m * 32 + mi * 16 + half * 8 + quad;
            float sv = s[co], bv = bias[co];
            #pragma unroll
            for (int ni = 0; ni < 4; ni++) {
                #pragma unroll
                for (int e = 0; e < 2; e++) {
                    int ridx = half * 2 + e;
                    float f = (float)acc1[mi][ni][ridx] * c1f
                            + (float)acc2[mi][ni][ridx] * c2f;
                    float y = fmaf(f, sv, bv);
                    int q = p0 + warp_n * 32 + ni * 8 + tq * 2 + e;
                    int n = q / IMG_PIX;
                    int rem = q - n * IMG_PIX;
                    int ph = rem / PDIM, pw = rem - ph * PDIM;
                    if ((unsigned)(ph - 1) < HIMG && (unsigned)(pw - 1) < WIMG)
                        out[((size_t)n * COUTCH + co) * HWSZ + (ph - 1) * WIMG + (pw - 1)] = y;
                }
            }
        }
    }
}

// ---------------- Host ----------------
extern "C" void kernel_launch(void* const* d_in, const int* in_sizes, int n_in,
                              void* d_out, int out_size) {
    const float* x    = (const float*)d_in[0];
    const int*   wq   = (const int*)d_in[1];
    const float* s    = (const float*)d_in[2];
    const float* bias = (const float*)d_in[3];
    float* out = (float*)d_out;

    cudaFuncSetAttribute(gemm_kernel, cudaFuncAttributeMaxDynamicSharedMemorySize, SMEM_TOTAL);

    prep_all_kernel<<<PREP_BLOCKS, 256>>>(x, wq);
    gemm_kernel<<<dim3(NTILES_B, 2), 256, SMEM_TOTAL>>>(s, bias, out);
}

// round 15
// speedup vs baseline: 1.4264x; 1.0134x over previous
#include <cuda_runtime.h>
#include <cstdint>

#define NIMG   32
#define CINCH  256
#define COUTCH 256
#define HIMG   56
#define WIMG   56
#define HWSZ   (HIMG*WIMG)           // 3136
#define PDIM   58
#define IMG_PIX (PDIM*PDIM)          // 3364
#define PIX    (NIMG*IMG_PIX)        // 107648
#define GUARD  64
#define TOT_ROWS (GUARD + PIX + GUARD)
#define XROW   512                   // bytes per X_t row: [a1:256 | a2:256]
#define AROW   2304                  // bytes per weight row (9*256)
#define NTILES_B 1682                // PIX / 64

#define BM 128
#define BN 64
#define NITER 18                     // 9 taps * 2 chunks of 128
#define SROW 144                     // padded smem row stride (ldmatrix conflict-free)
#define ST_A  0
#define ST_B1 (128*SROW)             // 18432
#define ST_B2 (ST_B1 + 64*SROW)      // 27648
#define STAGE_BYTES (ST_B2 + 64*SROW)   // 36864
#define SMEM_TOTAL (3*STAGE_BYTES)   // 110592

// fused prep block ranges
#define PXBLK (NIMG*HIMG)            // 1792
#define ZBLK  928                    // 7424 rows * 32 uint4 / 256
#define WBLK  2304                   // 589824 / 256
#define PREP_BLOCKS (PXBLK + ZBLK + WBLK)

__device__ __align__(256) char g_xt8[(size_t)TOT_ROWS * XROW];   // ~55.4 MB
__device__ __align__(256) char g_aw8[(size_t)COUTCH * AROW];     // ~590 KB

// ---------------- Fused prep kernel: prep_x | zero borders | prep_w ----------------
__global__ void __launch_bounds__(256) prep_all_kernel(const float* __restrict__ x,
                                                       const int* __restrict__ wq) {
    int b = blockIdx.x;
    int tid = threadIdx.x;
    if (b < PXBLK) {
        // ---- activation prep: clamp + 2-level int8 + transpose ----
        __shared__ char sp[56 * 516];
        int n = b / HIMG, h = b % HIMG;
        const float c1f = 1.0f / 127.0f;
        for (int idx = tid; idx < 256 * WIMG; idx += 256) {
            int ci = idx / WIMG, w = idx - ci * WIMG;
            float v = x[(((size_t)n * CINCH + ci) * HIMG + h) * WIMG + w];
            v = fminf(fmaxf(v, -1.0f), 1.0f);
            int a1 = __float2int_rn(v * 127.0f);
            float r = fmaf((float)a1, -c1f, v);
            int a2 = __float2int_rn(r * 32258.0f);
            a2 = max(-127, min(127, a2));
            sp[w * 516 + ci]       = (char)a1;
            sp[w * 516 + 256 + ci] = (char)a2;
        }
        __syncthreads();
        size_t rowbase = (size_t)GUARD + (size_t)n * IMG_PIX + (size_t)(h + 1) * PDIM + 1;
        for (int g = tid; g < 56 * 128; g += 256) {
            int w = g >> 7, wi = g & 127;
            uint32_t val = *(const uint32_t*)(sp + w * 516 + wi * 4);
            *(uint32_t*)(g_xt8 + (rowbase + w) * XROW + wi * 4) = val;
        }
    } else if (b < PXBLK + ZBLK) {
        // ---- zero guards + padded-border rows ----
        int t = (b - PXBLK) * 256 + tid;          // < 237568 = 7424*32
        int r = t >> 5, c = t & 31;
        size_t row;
        if (r < 64) row = (size_t)r;
        else if (r < 128) row = (size_t)GUARD + PIX + (r - 64);
        else {
            int rb = r - 128, n = rb / 228, bb = rb % 228;
            int ph, pw;
            if (bb < 58)        { ph = 0;            pw = bb; }
            else if (bb < 116)  { ph = 57;           pw = bb - 58; }
            else if (bb < 172)  { ph = bb - 116 + 1; pw = 0; }
            else                { ph = bb - 172 + 1; pw = 57; }
            row = (size_t)GUARD + (size_t)n * IMG_PIX + (size_t)ph * PDIM + pw;
        }
        ((uint4*)g_xt8)[row * 32 + c] = make_uint4(0, 0, 0, 0);
    } else {
        // ---- weight prep: int32 ternary -> int8, [co][tap*256+ci] ----
        int t = (b - PXBLK - ZBLK) * 256 + tid;   // < 589824
        int ci = t & 255, co = (t >> 8) & 255, tap = t >> 16;
        g_aw8[(size_t)co * AROW + tap * 256 + ci] = (char)wq[(co * 256 + ci) * 9 + tap];
    }
}

// ---------------- GEMM: int8 implicit conv, 256 thr, 4x2 warps, 2 CTAs/SM ----------------
__device__ __forceinline__ void mma_s8b(int* c, const uint32_t* a, uint32_t b0, uint32_t b1) {
    asm volatile(
        "mma.sync.aligned.m16n8k32.row.col.s32.s8.s8.s32 "
        "{%0,%1,%2,%3}, {%4,%5,%6,%7}, {%8,%9}, {%0,%1,%2,%3};"
        : "+r"(c[0]), "+r"(c[1]), "+r"(c[2]), "+r"(c[3])
        : "r"(a[0]), "r"(a[1]), "r"(a[2]), "r"(a[3]), "r"(b0), "r"(b1));
}
__device__ __forceinline__ void cp16(uint32_t dst, const void* src) {
    asm volatile("cp.async.cg.shared.global [%0], [%1], 16;" :: "r"(dst), "l"(src));
}
__device__ __forceinline__ void ldm_x4(uint32_t* r, uint32_t addr) {
    asm volatile("ldmatrix.sync.aligned.m8n8.x4.shared.b16 {%0,%1,%2,%3}, [%4];"
        : "=r"(r[0]), "=r"(r[1]), "=r"(r[2]), "=r"(r[3]) : "r"(addr));
}

__global__ void __launch_bounds__(256, 2)
gemm_kernel(const float* __restrict__ s, const float* __restrict__ bias,
            float* __restrict__ out)
{
    extern __shared__ char sm[];
    uint32_t smb = (uint32_t)__cvta_generic_to_shared(sm);
    int tid = threadIdx.x, lane = tid & 31, wid = tid >> 5;
    int quad = lane >> 2, tq = lane & 3;
    int warp_m = wid & 3, warp_n = wid >> 2;       // 4 x 2 warps: 32x32 warp tiles
    int p0 = blockIdx.x * BN;
    int co0 = blockIdx.y * BM;

    int lg = lane >> 3, lr = lane & 7;
    uint32_t laneoff = (uint32_t)(((lg & 1) * 8 + lr) * SROW + (lg >> 1) * 16);
    uint32_t a_base  = (uint32_t)(ST_A  + warp_m * 32 * SROW) + laneoff;
    uint32_t b1_base = (uint32_t)(ST_B1 + warp_n * 32 * SROW) + laneoff;
    uint32_t b2_base = (uint32_t)(ST_B2 + warp_n * 32 * SROW) + laneoff;

    int acc1[2][4][4], acc2[2][4][4];
    #pragma unroll
    for (int mi = 0; mi < 2; mi++)
        #pragma unroll
        for (int ni = 0; ni < 4; ni++)
            #pragma unroll
            for (int r = 0; r < 4; r++) { acc1[mi][ni][r] = 0; acc2[mi][ni][r] = 0; }

    // ---- strength-reduced loader state (per-thread invariant offsets) ----
    // chunk i=0..3 -> A rows r0+32i; i=4,5 -> B1 rows r0+{0,32}; i=6,7 -> B2 same rows +256B
    int r0 = tid >> 3;
    uint32_t ch16 = (uint32_t)(tid & 7) * 16;
    uint32_t ga_off[4], sa_off[4], gb_off[2], sb1_off[2], sb2_off[2];
    #pragma unroll
    for (int i = 0; i < 4; i++) {
        ga_off[i] = (uint32_t)(r0 + 32 * i) * AROW + ch16;
        sa_off[i] = (uint32_t)ST_A + (uint32_t)(r0 + 32 * i) * SROW + ch16;
    }
    #pragma unroll
    for (int j = 0; j < 2; j++) {
        gb_off[j]  = (uint32_t)(r0 + 32 * j) * XROW + ch16;
        sb1_off[j] = (uint32_t)ST_B1 + (uint32_t)(r0 + 32 * j) * SROW + ch16;
        sb2_off[j] = (uint32_t)ST_B2 + (uint32_t)(r0 + 32 * j) * SROW + ch16;
    }
    // running bases: a advances +128/iter; b per-iter delta handles kc + tap shifts
    const char* a_ptr = g_aw8 + (size_t)co0 * AROW;
    const char* b_ptr = g_xt8 + (size_t)(GUARD + p0 - 59) * XROW;   // tapoff(0) = -59
    uint32_t sb_iss = smb;          // smem stage base for next issued iteration
    int iss = 0;                    // next iteration index to issue

    auto issue2 = [&]() {
        #pragma unroll
        for (int i = 0; i < 4; i++)
            cp16(sb_iss + sa_off[i], a_ptr + ga_off[i]);
        cp16(sb_iss + sb1_off[0], b_ptr + gb_off[0]);
        cp16(sb_iss + sb1_off[1], b_ptr + gb_off[1]);
        cp16(sb_iss + sb2_off[0], b_ptr + gb_off[0] + 256);
        cp16(sb_iss + sb2_off[1], b_ptr + gb_off[1] + 256);
        // advance state for next issue
        a_ptr += 128;
        if ((iss & 1) == 0) {
            b_ptr += 128;
        } else {
            int tap = iss >> 1;
            int dtap = (tap - (tap / 3) * 3 == 2) ? 56 : 1;
            b_ptr += (size_t)dtap * XROW - 128;
        }
        sb_iss += STAGE_BYTES;
        if (sb_iss == smb + 3 * STAGE_BYTES) sb_iss = smb;
        iss++;
    };

    issue2(); asm volatile("cp.async.commit_group;" ::: "memory");
    issue2(); asm volatile("cp.async.commit_group;" ::: "memory");

    uint32_t stb = smb;             // compute-side stage base
    for (int it = 0; it < NITER; it++) {
        asm volatile("cp.async.wait_group 1;" ::: "memory");
        __syncthreads();

        uint32_t sa = stb + a_base, s1 = stb + b1_base, s2 = stb + b2_base;
        stb += STAGE_BYTES;
        if (stb == smb + 3 * STAGE_BYTES) stb = smb;

        // double-buffered fragments: prefetch ks+1 while ks's MMAs run
        uint32_t af[2][2][4], bf[2][4][4];

        // prefetch ks = 0
        ldm_x4(af[0][0], sa);
        ldm_x4(af[0][1], sa + 16 * SROW);
        ldm_x4(bf[0][0], s1);
        ldm_x4(bf[0][1], s1 + 16 * SROW);
        ldm_x4(bf[0][2], s2);
        ldm_x4(bf[0][3], s2 + 16 * SROW);

        // next-stage global->smem copies overlap with fragment latency + MMAs
        if (it + 2 < NITER) issue2();
        asm volatile("cp.async.commit_group;" ::: "memory");

        #pragma unroll
        for (int ks = 0; ks < 4; ks++) {
            const int c = ks & 1, nx = c ^ 1;
            if (ks < 3) {
                uint32_t kof = (uint32_t)(ks + 1) * 32;
                ldm_x4(af[nx][0], sa + kof);
                ldm_x4(af[nx][1], sa + 16 * SROW + kof);
                ldm_x4(bf[nx][0], s1 + kof);
                ldm_x4(bf[nx][1], s1 + 16 * SROW + kof);
                ldm_x4(bf[nx][2], s2 + kof);
                ldm_x4(bf[nx][3], s2 + 16 * SROW + kof);
            }
            #pragma unroll
            for (int mi = 0; mi < 2; mi++) {
                mma_s8b(acc1[mi][0], af[c][mi], bf[c][0][0], bf[c][0][2]);
                mma_s8b(acc1[mi][1], af[c][mi], bf[c][0][1], bf[c][0][3]);
                mma_s8b(acc1[mi][2], af[c][mi], bf[c][1][0], bf[c][1][2]);
                mma_s8b(acc1[mi][3], af[c][mi], bf[c][1][1], bf[c][1][3]);
                mma_s8b(acc2[mi][0], af[c][mi], bf[c][2][0], bf[c][2][2]);
                mma_s8b(acc2[mi][1], af[c][mi], bf[c][2][1], bf[c][2][3]);
                mma_s8b(acc2[mi][2], af[c][mi], bf[c][3][0], bf[c][3][2]);
                mma_s8b(acc2[mi][3], af[c][mi], bf[c][3][1], bf[c][3][3]);
            }
        }
    }

    // ---- epilogue: combine planes, scale+bias, scatter to NCHW ----
    const float c1f = 1.0f / 127.0f;
    const float c2f = 1.0f / 32258.0f;
    #pragma unroll
    for (int mi = 0; mi < 2; mi++) {
        #pragma unroll
        for (int half = 0; half < 2; half++) {
            int co = co0 + warp_m * 32 + mi * 16 + half * 8 + quad;
            float sv = s[co], bv = bias[co];
            #pragma unroll
            for (int ni = 0; ni < 4; ni++) {
                #pragma unroll
                for (int e = 0; e < 2; e++) {
                    int ridx = half * 2 + e;
                    float f = (float)acc1[mi][ni][ridx] * c1f
                            + (float)acc2[mi][ni][ridx] * c2f;
                    float y = fmaf(f, sv, bv);
                    int q = p0 + warp_n * 32 + ni * 8 + tq * 2 + e;
                    int n = q / IMG_PIX;
                    int rem = q - n * IMG_PIX;
                    int ph = rem / PDIM, pw = rem - ph * PDIM;
                    if ((unsigned)(ph - 1) < HIMG && (unsigned)(pw - 1) < WIMG)
                        out[((size_t)n * COUTCH + co) * HWSZ + (ph - 1) * WIMG + (pw - 1)] = y;
                }
            }
        }
    }
}

// ---------------- Host ----------------
extern "C" void kernel_launch(void* const* d_in, const int* in_sizes, int n_in,
                              void* d_out, int out_size) {
    const float* x    = (const float*)d_in[0];
    const int*   wq   = (const int*)d_in[1];
    const float* s    = (const float*)d_in[2];
    const float* bias = (const float*)d_in[3];
    float* out = (float*)d_out;

    cudaFuncSetAttribute(gemm_kernel, cudaFuncAttributeMaxDynamicSharedMemorySize, SMEM_TOTAL);

    prep_all_kernel<<<PREP_BLOCKS, 256>>>(x, wq);
    gemm_kernel<<<dim3(NTILES_B, 2), 256, SMEM_TOTAL>>>(s, bias, out);
}